// round 1
// baseline (speedup 1.0000x reference)
#include <cuda_runtime.h>
#include <math.h>

#define B_ 2
#define H_ 16
#define S_ 2048
#define D_ 72
#define BHS_ (B_*H_*S_)

#define NT 256
#define LDP 68
#define LDV 80
#define LDST 77

// scratch: rotated + normalized q and k (allowed: __device__ globals, no runtime alloc)
__device__ float g_qr[BHS_*D_];
__device__ float g_kr[BHS_*D_];

// ---------------------------------------------------------------------------
// Kernel 1: fingerprint-RoPE + L2 normalize for q and k.
// One warp per (b,h,s) row. 30 angles per row; rotation preserves layout:
//   out[d]       = x[d]*c[d] - x[d+30]*s[d]        d in [0,30)
//   out[d]       = x[d]*c[d-30] + x[d-30]*s[d-30]  d in [30,60)
//   out[d]       = x[d]                            d in [60,72)
// Then x *= sqrt(scale[h]) * rsqrt(sum(x^2)+1e-6).
// ---------------------------------------------------------------------------
__global__ void prep_kernel(const float* __restrict__ q, const float* __restrict__ k,
                            const float* __restrict__ pos, const float* __restrict__ pos_orig,
                            const float* __restrict__ tim, const float* __restrict__ freqs,
                            const float* __restrict__ t_freqs, const float* __restrict__ scale)
{
    int gid  = blockIdx.x*blockDim.x + threadIdx.x;
    int wid  = gid >> 5;
    int lane = gid & 31;
    if (wid >= BHS_) return;
    int s = wid & (S_-1);
    int h = (wid >> 11) & (H_-1);
    int b = wid >> 15;
    int bs = b*S_ + s;

    float px  = pos[bs*2+0]*2.f - 1.f;
    float py  = pos[bs*2+1]*2.f - 1.f;
    float pxo = pos_orig[bs*2+0]*2.f - 1.f;
    float pyo = pos_orig[bs*2+1]*2.f - 1.f;
    float tm  = tim[bs];

    // theta layout (30): [th_h(orig), th_h(new), th_w(orig), th_w(new), th_t] x 6
    float cv = 1.f, sv = 0.f;
    if (lane < 30) {
        int m = lane / 6, j = lane % 6;
        float th;
        if      (m == 0) th = pyo * freqs[96 + h*6 + j];   // freqs[1]
        else if (m == 1) th = py  * freqs[96 + h*6 + j];
        else if (m == 2) th = pxo * freqs[h*6 + j];        // freqs[0]
        else if (m == 3) th = px  * freqs[h*6 + j];
        else             th = tm  * t_freqs[h*6 + j];
        sincosf(th, &sv, &cv);
    }
    int idxA = (lane < 30) ? lane : (lane - 30);
    int idxB = (lane < 28) ? (lane + 2) : 0;
    float cA = __shfl_sync(0xffffffffu, cv, idxA);
    float sA = __shfl_sync(0xffffffffu, sv, idxA);
    float cB = __shfl_sync(0xffffffffu, cv, idxB);
    float sB = __shfl_sync(0xffffffffu, sv, idxB);

    float fac_scale = sqrtf(scale[h]);
    size_t rowoff = (size_t)wid * D_;

    #pragma unroll
    for (int which = 0; which < 2; which++) {
        const float* xr = (which == 0 ? q : k) + rowoff;
        float* xo = (which == 0 ? g_qr : g_kr) + rowoff;

        float xa = xr[lane];
        float xb = xr[lane+32];
        float xc = (lane < 8) ? xr[lane+64] : 0.f;
        float xpa = (lane < 30) ? xr[lane+30] : xr[lane-30];
        float xpb = (lane < 28) ? xr[lane+2]  : 0.f;

        // d = lane: lanes 0..29 are x1-side; lanes 30,31 are x2-side (d in [30,60))
        float oa = (lane < 30) ? (xa*cA - xpa*sA) : (xa*cA + xpa*sA);
        // d = lane+32: lanes 0..27 are x2-side; lanes 28..31 passthrough (d >= 60)
        float ob = (lane < 28) ? (xb*cB + xpb*sB) : xb;
        float oc = xc;

        float ss = oa*oa + ob*ob + oc*oc;
        #pragma unroll
        for (int mm = 16; mm >= 1; mm >>= 1)
            ss += __shfl_xor_sync(0xffffffffu, ss, mm);
        float fac = fac_scale * rsqrtf(ss + 1e-6f);

        xo[lane]    = oa*fac;
        xo[lane+32] = ob*fac;
        if (lane < 8) xo[lane+64] = oc*fac;
    }
}

// ---------------------------------------------------------------------------
// Kernel 2: flash attention over the block mask.
// Grid: (32 q-tiles, B*H). q-tiles 0..8 -> zero output. 9..16 causal,
// 17..31 prefix(17 full k-tiles) + diagonal-only self tile.
// 256 threads. Stage1: 64x64 scores, 4x4 frags (16x16 thread grid),
// operands from d-major transposed smem (conflict-free float4 reads).
// Stage2: P@V with thread = (row, 20-col group), V padded to 80 cols.
// ---------------------------------------------------------------------------
__global__ void __launch_bounds__(256, 2)
attn_kernel(const float* __restrict__ v, float* __restrict__ out)
{
    int qt  = blockIdx.x;
    int bh  = blockIdx.y;
    int tid = threadIdx.x;
    float* obase = out + (size_t)bh*S_*D_;
    int q0 = qt*64;

    if (qt < 9) {  // fully masked rows -> zeros
        for (int i = tid; i < 64*D_; i += NT) obase[q0*D_ + i] = 0.f;
        return;
    }

    extern __shared__ float sm[];
    float* QsT  = sm;                  // [72][64] d-major
    float* KsT  = QsT + D_*64;         // [72][64] d-major
    float* Vs   = KsT + D_*64;         // [64][80]
    float* Ps   = Vs  + 64*LDV;        // [64][68]
    float* Kst  = Ps  + 64*LDP;        // [64][77] staging for transpose
    float* rowm = Kst + 64*LDST;       // [64]
    float* rowl = rowm + 64;           // [64]
    float* rowa = rowl + 64;           // [64]

    const float* vbase = v    + (size_t)bh*S_*D_;
    const float* qbase = g_qr + (size_t)bh*S_*D_;
    const float* kbase = g_kr + (size_t)bh*S_*D_;

    // Load Q tile (coalesced) into staging, zero V pad, init row stats
    for (int i = tid; i < 64*D_; i += NT) {
        int r = i / D_, d = i - r*D_;
        Kst[r*LDST + d] = qbase[(size_t)(q0 + r)*D_ + d];
    }
    if (tid < 64) { rowm[tid] = -1e30f; rowl[tid] = 0.f; }
    for (int i = tid; i < 64*8; i += NT) {
        int r = i >> 3, d = 72 + (i & 7);
        Vs[r*LDV + d] = 0.f;
    }
    __syncthreads();
    for (int i = tid; i < 64*D_; i += NT) {
        int r = i & 63, d = i >> 6;
        QsT[d*64 + r] = Kst[r*LDST + d];
    }

    float acc[20];
    #pragma unroll
    for (int i = 0; i < 20; i++) acc[i] = 0.f;

    int orow = tid >> 2;          // stage2 row
    int cg   = tid & 3;           // stage2 col group (20 cols each)
    int ty = tid >> 4, tx = tid & 15;
    int r0 = ty*4, c0 = tx*4;

    bool causal = (qt <= 16);
    int nkt = causal ? (qt + 1) : 18;
    const float L2E = 1.4426950408889634f;

    for (int kti = 0; kti < nkt; kti++) {
        int  kt    = (!causal && kti == 17) ? qt : kti;
        bool diagC = causal && (kti == qt);     // causal diagonal tile
        bool diagS = (!causal && kti == 17);    // self-only tile
        int  k0    = kt*64;

        __syncthreads();   // prior stage2 done before overwriting Kst/Vs
        for (int i = tid; i < 64*D_; i += NT) {
            int r = i / D_, d = i - r*D_;
            Kst[r*LDST + d] = kbase[(size_t)(k0 + r)*D_ + d];
            Vs[r*LDV + d]   = vbase[(size_t)(k0 + r)*D_ + d];
        }
        __syncthreads();
        for (int i = tid; i < 64*D_; i += NT) {
            int r = i & 63, d = i >> 6;
            KsT[d*64 + r] = Kst[r*LDST + d];
        }
        __syncthreads();

        // ---- stage 1: S = Q @ K^T (4x4 fragment per thread) ----
        float sf[4][4];
        #pragma unroll
        for (int i = 0; i < 4; i++)
            #pragma unroll
            for (int j = 0; j < 4; j++) sf[i][j] = 0.f;

        #pragma unroll 4
        for (int kk = 0; kk < D_; kk++) {
            float4 qv = *(const float4*)(QsT + kk*64 + r0);
            float4 kv = *(const float4*)(KsT + kk*64 + c0);
            float qq[4] = {qv.x, qv.y, qv.z, qv.w};
            float kw[4] = {kv.x, kv.y, kv.z, kv.w};
            #pragma unroll
            for (int i = 0; i < 4; i++)
                #pragma unroll
                for (int j = 0; j < 4; j++)
                    sf[i][j] = fmaf(qq[i], kw[j], sf[i][j]);
        }

        if (diagC) {
            #pragma unroll
            for (int i = 0; i < 4; i++)
                #pragma unroll
                for (int j = 0; j < 4; j++)
                    if (c0 + j > r0 + i) sf[i][j] = -1e30f;
        } else if (diagS) {
            #pragma unroll
            for (int i = 0; i < 4; i++)
                #pragma unroll
                for (int j = 0; j < 4; j++)
                    if (c0 + j != r0 + i) sf[i][j] = -1e30f;
        }

        // ---- online softmax ----
        float mx[4], mo[4], mn[4], rs[4];
        #pragma unroll
        for (int i = 0; i < 4; i++) {
            float m0 = fmaxf(fmaxf(sf[i][0], sf[i][1]), fmaxf(sf[i][2], sf[i][3]));
            #pragma unroll
            for (int mm = 8; mm >= 1; mm >>= 1)
                m0 = fmaxf(m0, __shfl_xor_sync(0xffffffffu, m0, mm));
            mx[i] = m0;
        }
        #pragma unroll
        for (int i = 0; i < 4; i++) {
            mo[i] = rowm[r0+i];
            mn[i] = fmaxf(mo[i], mx[i]);
        }
        #pragma unroll
        for (int i = 0; i < 4; i++) {
            float p0 = exp2f((sf[i][0]-mn[i])*L2E);
            float p1 = exp2f((sf[i][1]-mn[i])*L2E);
            float p2 = exp2f((sf[i][2]-mn[i])*L2E);
            float p3 = exp2f((sf[i][3]-mn[i])*L2E);
            rs[i] = (p0+p1) + (p2+p3);
            *(float4*)(Ps + (r0+i)*LDP + c0) = make_float4(p0,p1,p2,p3);
        }
        #pragma unroll
        for (int i = 0; i < 4; i++) {
            float r_ = rs[i];
            #pragma unroll
            for (int mm = 8; mm >= 1; mm >>= 1)
                r_ += __shfl_xor_sync(0xffffffffu, r_, mm);
            rs[i] = r_;
        }
        __syncwarp();   // all reads of rowm/rowl precede the tx==0 writes
        if (tx == 0) {
            #pragma unroll
            for (int i = 0; i < 4; i++) {
                float a = exp2f((mo[i]-mn[i])*L2E);
                rowa[r0+i] = a;
                rowm[r0+i] = mn[i];
                rowl[r0+i] = rowl[r0+i]*a + rs[i];
            }
        }
        __syncthreads();

        // ---- stage 2: O = O*alpha + P @ V ----
        float alpha = rowa[orow];
        #pragma unroll
        for (int i = 0; i < 20; i++) acc[i] *= alpha;

        #pragma unroll 2
        for (int k4 = 0; k4 < 64; k4 += 4) {
            float4 pv = *(const float4*)(Ps + orow*LDP + k4);
            float pp[4] = {pv.x, pv.y, pv.z, pv.w};
            #pragma unroll
            for (int u = 0; u < 4; u++) {
                #pragma unroll
                for (int i5 = 0; i5 < 5; i5++) {
                    float4 vv = *(const float4*)(Vs + (k4+u)*LDV + cg*20 + i5*4);
                    acc[i5*4+0] = fmaf(pp[u], vv.x, acc[i5*4+0]);
                    acc[i5*4+1] = fmaf(pp[u], vv.y, acc[i5*4+1]);
                    acc[i5*4+2] = fmaf(pp[u], vv.z, acc[i5*4+2]);
                    acc[i5*4+3] = fmaf(pp[u], vv.w, acc[i5*4+3]);
                }
            }
        }
    }

    __syncthreads();
    float invl = 1.f / rowl[orow];
    #pragma unroll
    for (int i = 0; i < 20; i++) {
        int c = cg*20 + i;
        if (c < 72)
            obase[(size_t)(q0 + orow)*D_ + c] = acc[i]*invl;
    }
}

extern "C" void kernel_launch(void* const* d_in, const int* in_sizes, int n_in,
                              void* d_out, int out_size)
{
    const float* q        = (const float*)d_in[0];
    const float* k        = (const float*)d_in[1];
    const float* v        = (const float*)d_in[2];
    const float* pos      = (const float*)d_in[3];
    const float* pos_orig = (const float*)d_in[4];
    const float* tim      = (const float*)d_in[5];
    const float* freqs    = (const float*)d_in[6];
    const float* t_freqs  = (const float*)d_in[7];
    const float* scale    = (const float*)d_in[8];
    float* out = (float*)d_out;

    const int smem_bytes = (D_*64 + D_*64 + 64*LDV + 64*LDP + 64*LDST + 192) * 4;
    cudaFuncSetAttribute(attn_kernel, cudaFuncAttributeMaxDynamicSharedMemorySize, smem_bytes);

    int total_threads = BHS_ * 32;
    prep_kernel<<<total_threads / 256, 256>>>(q, k, pos, pos_orig, tim, freqs, t_freqs, scale);

    dim3 grid(S_/64, B_*H_);
    attn_kernel<<<grid, NT, smem_bytes>>>(v, out);
}

// round 2
// speedup vs baseline: 1.6253x; 1.6253x over previous
#include <cuda_runtime.h>
#include <math.h>

#define B_ 2
#define H_ 16
#define S_ 2048
#define D_ 72
#define BHS_ (B_*H_*S_)

#define NT 256
#define LDK 68   // VsT row stride (VsT[d][r], d<80)
#define LDP 64   // Ps row stride  (Ps[r][kk])

// scratch: rotated + normalized q and k, TRANSPOSED per head: [bh][d][s]
__device__ float g_qrT[BHS_*D_];
__device__ float g_krT[BHS_*D_];

// ---------------------------------------------------------------------------
// Kernel 1: fingerprint-RoPE + L2 normalize; outputs d-major (transposed).
// Block = 256 threads = 8 warps; covers 32 consecutive s rows of one (b,h).
// Each warp processes 4 rows, results staged in smem, written coalesced.
// ---------------------------------------------------------------------------
__global__ void prep_kernel(const float* __restrict__ q, const float* __restrict__ k,
                            const float* __restrict__ pos, const float* __restrict__ pos_orig,
                            const float* __restrict__ tim, const float* __restrict__ freqs,
                            const float* __restrict__ t_freqs, const float* __restrict__ scale)
{
    __shared__ float sq[72*33];
    __shared__ float sk[72*33];

    int tid  = threadIdx.x;
    int wrp  = tid >> 5;
    int lane = tid & 31;
    int row0 = blockIdx.x * 32;           // first global row (wid) of this block
    int bh   = row0 >> 11;                // b*H + h
    int h    = bh & (H_-1);
    int s0   = row0 & (S_-1);

    float fac_scale = sqrtf(scale[h]);

    for (int r = 0; r < 4; r++) {
        int sl  = wrp*4 + r;              // local row 0..31
        int wid = row0 + sl;
        int s   = s0 + sl;
        int b   = bh >> 4;
        int bs  = b*S_ + s;

        float px  = pos[bs*2+0]*2.f - 1.f;
        float py  = pos[bs*2+1]*2.f - 1.f;
        float pxo = pos_orig[bs*2+0]*2.f - 1.f;
        float pyo = pos_orig[bs*2+1]*2.f - 1.f;
        float tm  = tim[bs];

        float cv = 1.f, sv = 0.f;
        if (lane < 30) {
            int m = lane / 6, j = lane % 6;
            float th;
            if      (m == 0) th = pyo * freqs[96 + h*6 + j];
            else if (m == 1) th = py  * freqs[96 + h*6 + j];
            else if (m == 2) th = pxo * freqs[h*6 + j];
            else if (m == 3) th = px  * freqs[h*6 + j];
            else             th = tm  * t_freqs[h*6 + j];
            sincosf(th, &sv, &cv);
        }
        int idxA = (lane < 30) ? lane : (lane - 30);
        int idxB = (lane < 28) ? (lane + 2) : 0;
        float cA = __shfl_sync(0xffffffffu, cv, idxA);
        float sA = __shfl_sync(0xffffffffu, sv, idxA);
        float cB = __shfl_sync(0xffffffffu, cv, idxB);
        float sB = __shfl_sync(0xffffffffu, sv, idxB);

        size_t rowoff = (size_t)wid * D_;
        #pragma unroll
        for (int which = 0; which < 2; which++) {
            const float* xr = (which == 0 ? q : k) + rowoff;
            float* so = (which == 0 ? sq : sk);

            float xa = xr[lane];
            float xb = xr[lane+32];
            float xc = (lane < 8) ? xr[lane+64] : 0.f;
            float xpa = (lane < 30) ? xr[lane+30] : xr[lane-30];
            float xpb = (lane < 28) ? xr[lane+2]  : 0.f;

            float oa = (lane < 30) ? (xa*cA - xpa*sA) : (xa*cA + xpa*sA);
            float ob = (lane < 28) ? (xb*cB + xpb*sB) : xb;
            float oc = xc;

            float ss = oa*oa + ob*ob + oc*oc;
            #pragma unroll
            for (int mm = 16; mm >= 1; mm >>= 1)
                ss += __shfl_xor_sync(0xffffffffu, ss, mm);
            float fac = fac_scale * rsqrtf(ss + 1e-6f);

            so[lane*33 + sl]      = oa*fac;
            so[(lane+32)*33 + sl] = ob*fac;
            if (lane < 8) so[(lane+64)*33 + sl] = oc*fac;
        }
    }
    __syncthreads();

    // coalesced transposed write: [bh][d][s]
    size_t obase = (size_t)bh * D_ * S_ + s0;
    for (int i = tid; i < 72*32; i += NT) {
        int d = i >> 5, sl = i & 31;
        g_qrT[obase + (size_t)d*S_ + sl] = sq[d*33 + sl];
        g_krT[obase + (size_t)d*S_ + sl] = sk[d*33 + sl];
    }
}

// ---------------------------------------------------------------------------
// Kernel 2: flash attention over the block mask.
// q-tiles 0..8 -> zeros. 9..16 causal (tiles 0..qt, diag triangular).
// 17..31: 17 full prefix tiles + diagonal-only self tile (fast path).
// stage1: 64x64 scores, 4x4 frags; stage2: O += P@V, 4x5 frags, V transposed.
// ---------------------------------------------------------------------------
__global__ void __launch_bounds__(256, 3)
attn_kernel(const float* __restrict__ v, float* __restrict__ out)
{
    int qt  = blockIdx.x;
    int bh  = blockIdx.y;
    int tid = threadIdx.x;
    float* obase = out + (size_t)bh*S_*D_;
    int q0 = qt*64;

    if (qt < 9) {
        for (int i = tid; i < 64*D_; i += NT) obase[q0*D_ + i] = 0.f;
        return;
    }

    extern __shared__ float sm[];
    float* QsT  = sm;                 // [72][64] d-major
    float* KsT  = QsT + 72*64;        // [72][64] d-major
    float* VsT  = KsT + 72*64;        // [80][68] d-major (rows 72..79 zero)
    float* Ps   = VsT + 80*LDK;       // [64][64] row-major
    float* rowm = Ps  + 64*LDP;
    float* rowl = rowm + 64;
    float* rowa = rowl + 64;
    float* srr  = rowa + 64;

    const float* vbase = v     + (size_t)bh*S_*D_;
    const float* qbase = g_qrT + (size_t)bh*D_*S_;
    const float* kbase = g_krT + (size_t)bh*D_*S_;

    // Q tile (coalesced, d-major direct), V pad rows, stats init
    for (int i = tid; i < 72*64; i += NT) {
        // i = d*64 + r
        QsT[i] = qbase[(size_t)(i >> 6)*S_ + q0 + (i & 63)];
    }
    if (tid < 64) { rowm[tid] = -1e30f; rowl[tid] = 0.f; }
    for (int i = tid; i < 8*LDK; i += NT) VsT[72*LDK + i] = 0.f;

    float acc[20];
    #pragma unroll
    for (int i = 0; i < 20; i++) acc[i] = 0.f;

    int ty = tid >> 4, tx = tid & 15;
    int r0  = ty*4;        // rows (both stages)
    int c0  = tx*4;        // stage1 cols
    int c02 = tx*5;        // stage2 cols (over 80 padded)

    bool causal = (qt <= 16);
    int nkt = causal ? (qt + 1) : 18;
    const float L2E = 1.4426950408889634f;

    for (int kti = 0; kti < nkt; kti++) {
        bool diagC = causal && (kti == qt);
        bool diagS = (!causal && kti == 17);
        int  kt    = diagS ? qt : kti;
        int  k0    = kt*64;

        __syncthreads();   // previous stage reads of KsT/VsT done
        for (int i = tid; i < 72*64; i += NT)
            KsT[i] = kbase[(size_t)(i >> 6)*S_ + k0 + (i & 63)];
        for (int i = tid; i < 64*72; i += NT) {
            int r = i / 72, d = i - r*72;
            VsT[d*LDK + r] = vbase[(size_t)(k0 + r)*D_ + d];
        }
        __syncthreads();

        if (diagS) {
            // ---- fast path: only the diagonal of this tile is unmasked ----
            if (tid < 64) {
                float s_ = 0.f;
                #pragma unroll 8
                for (int d = 0; d < D_; d++)
                    s_ = fmaf(QsT[d*64 + tid], KsT[d*64 + tid], s_);
                float mo = rowm[tid];
                float mn = fmaxf(mo, s_);
                float a  = exp2f((mo - mn)*L2E);
                float p  = exp2f((s_ - mn)*L2E);
                rowa[tid] = a;
                srr[tid]  = p;
                rowm[tid] = mn;
                rowl[tid] = rowl[tid]*a + p;
            }
            __syncthreads();
            #pragma unroll
            for (int i = 0; i < 4; i++) {
                float a = rowa[r0+i];
                float p = srr[r0+i];
                #pragma unroll
                for (int j = 0; j < 5; j++)
                    acc[i*5+j] = acc[i*5+j]*a + p * VsT[(c02+j)*LDK + (r0+i)];
            }
            continue;
        }

        // ---- stage 1: S = Q @ K^T ----
        float sf[4][4];
        #pragma unroll
        for (int i = 0; i < 4; i++)
            #pragma unroll
            for (int j = 0; j < 4; j++) sf[i][j] = 0.f;

        #pragma unroll 4
        for (int kk = 0; kk < D_; kk++) {
            float4 qv = *(const float4*)(QsT + kk*64 + r0);
            float4 kv = *(const float4*)(KsT + kk*64 + c0);
            float qq[4] = {qv.x, qv.y, qv.z, qv.w};
            float kw[4] = {kv.x, kv.y, kv.z, kv.w};
            #pragma unroll
            for (int i = 0; i < 4; i++)
                #pragma unroll
                for (int j = 0; j < 4; j++)
                    sf[i][j] = fmaf(qq[i], kw[j], sf[i][j]);
        }

        if (diagC) {
            #pragma unroll
            for (int i = 0; i < 4; i++)
                #pragma unroll
                for (int j = 0; j < 4; j++)
                    if (c0 + j > r0 + i) sf[i][j] = -1e30f;
        }

        // ---- online softmax ----
        float mo[4], mn[4], rs[4];
        #pragma unroll
        for (int i = 0; i < 4; i++) {
            float m0 = fmaxf(fmaxf(sf[i][0], sf[i][1]), fmaxf(sf[i][2], sf[i][3]));
            #pragma unroll
            for (int mm = 8; mm >= 1; mm >>= 1)
                m0 = fmaxf(m0, __shfl_xor_sync(0xffffffffu, m0, mm));
            mo[i] = rowm[r0+i];
            mn[i] = fmaxf(mo[i], m0);
        }
        #pragma unroll
        for (int i = 0; i < 4; i++) {
            float p0 = exp2f((sf[i][0]-mn[i])*L2E);
            float p1 = exp2f((sf[i][1]-mn[i])*L2E);
            float p2 = exp2f((sf[i][2]-mn[i])*L2E);
            float p3 = exp2f((sf[i][3]-mn[i])*L2E);
            rs[i] = (p0+p1) + (p2+p3);
            *(float4*)(Ps + (r0+i)*LDP + c0) = make_float4(p0,p1,p2,p3);
        }
        #pragma unroll
        for (int i = 0; i < 4; i++) {
            float r_ = rs[i];
            #pragma unroll
            for (int mm = 8; mm >= 1; mm >>= 1)
                r_ += __shfl_xor_sync(0xffffffffu, r_, mm);
            rs[i] = r_;
        }
        __syncwarp();
        if (tx == 0) {
            #pragma unroll
            for (int i = 0; i < 4; i++) {
                float a = exp2f((mo[i]-mn[i])*L2E);
                rowa[r0+i] = a;
                rowm[r0+i] = mn[i];
                rowl[r0+i] = rowl[r0+i]*a + rs[i];
            }
        }
        __syncthreads();

        // ---- stage 2: O = O*alpha + P @ V  (4x5 frags, vectorized) ----
        #pragma unroll
        for (int i = 0; i < 4; i++) {
            float a = rowa[r0+i];
            #pragma unroll
            for (int j = 0; j < 5; j++) acc[i*5+j] *= a;
        }

        #pragma unroll 2
        for (int k4 = 0; k4 < 64; k4 += 4) {
            float4 pv[4];
            #pragma unroll
            for (int i = 0; i < 4; i++)
                pv[i] = *(const float4*)(Ps + (r0+i)*LDP + k4);
            #pragma unroll
            for (int j = 0; j < 5; j++) {
                float4 vv = *(const float4*)(VsT + (c02+j)*LDK + k4);
                #pragma unroll
                for (int i = 0; i < 4; i++) {
                    acc[i*5+j] = fmaf(pv[i].x, vv.x, acc[i*5+j]);
                    acc[i*5+j] = fmaf(pv[i].y, vv.y, acc[i*5+j]);
                    acc[i*5+j] = fmaf(pv[i].z, vv.z, acc[i*5+j]);
                    acc[i*5+j] = fmaf(pv[i].w, vv.w, acc[i*5+j]);
                }
            }
        }
    }

    __syncthreads();
    #pragma unroll
    for (int i = 0; i < 4; i++) {
        float invl = 1.f / rowl[r0+i];
        #pragma unroll
        for (int j = 0; j < 5; j++) {
            int c = c02 + j;
            if (c < D_)
                obase[(size_t)(q0 + r0 + i)*D_ + c] = acc[i*5+j]*invl;
        }
    }
}

extern "C" void kernel_launch(void* const* d_in, const int* in_sizes, int n_in,
                              void* d_out, int out_size)
{
    const float* q        = (const float*)d_in[0];
    const float* k        = (const float*)d_in[1];
    const float* v        = (const float*)d_in[2];
    const float* pos      = (const float*)d_in[3];
    const float* pos_orig = (const float*)d_in[4];
    const float* tim      = (const float*)d_in[5];
    const float* freqs    = (const float*)d_in[6];
    const float* t_freqs  = (const float*)d_in[7];
    const float* scale    = (const float*)d_in[8];
    float* out = (float*)d_out;

    const int smem_bytes = (72*64 + 72*64 + 80*LDK + 64*LDP + 256) * 4;  // 76032 B
    cudaFuncSetAttribute(attn_kernel, cudaFuncAttributeMaxDynamicSharedMemorySize, smem_bytes);

    prep_kernel<<<BHS_/32, NT>>>(q, k, pos, pos_orig, tim, freqs, t_freqs, scale);

    dim3 grid(S_/64, B_*H_);
    attn_kernel<<<grid, NT, smem_bytes>>>(v, out);
}

// round 3
// speedup vs baseline: 1.6303x; 1.0031x over previous
#include <cuda_runtime.h>
#include <math.h>

#define B_ 2
#define H_ 16
#define S_ 2048
#define D_ 72
#define BHS_ (B_*H_*S_)

#define NT 256
#define LDK 68   // VsT row stride (VsT[d][r], d<80)
#define LDP 64   // Ps row stride  (Ps[r][kk])

// scratch: rotated + normalized q and k, TRANSPOSED per head: [bh][d][s]
__device__ float g_qrT[BHS_*D_];
__device__ float g_krT[BHS_*D_];

// ---------------------------------------------------------------------------
// Kernel 1: fingerprint-RoPE + L2 normalize; outputs d-major (transposed).
// Block = 256 threads = 8 warps; covers 32 consecutive s rows of one (b,h).
// Each warp processes 4 rows, results staged in smem, written coalesced.
// ---------------------------------------------------------------------------
__global__ void prep_kernel(const float* __restrict__ q, const float* __restrict__ k,
                            const float* __restrict__ pos, const float* __restrict__ pos_orig,
                            const float* __restrict__ tim, const float* __restrict__ freqs,
                            const float* __restrict__ t_freqs, const float* __restrict__ scale)
{
    __shared__ float sq[72*33];
    __shared__ float sk[72*33];

    int tid  = threadIdx.x;
    int wrp  = tid >> 5;
    int lane = tid & 31;
    int row0 = blockIdx.x * 32;           // first global row (wid) of this block
    int bh   = row0 >> 11;                // b*H + h
    int h    = bh & (H_-1);
    int s0   = row0 & (S_-1);

    float fac_scale = sqrtf(scale[h]);

    for (int r = 0; r < 4; r++) {
        int sl  = wrp*4 + r;              // local row 0..31
        int wid = row0 + sl;
        int s   = s0 + sl;
        int b   = bh >> 4;
        int bs  = b*S_ + s;

        float px  = pos[bs*2+0]*2.f - 1.f;
        float py  = pos[bs*2+1]*2.f - 1.f;
        float pxo = pos_orig[bs*2+0]*2.f - 1.f;
        float pyo = pos_orig[bs*2+1]*2.f - 1.f;
        float tm  = tim[bs];

        float cv = 1.f, sv = 0.f;
        if (lane < 30) {
            int m = lane / 6, j = lane % 6;
            float th;
            if      (m == 0) th = pyo * freqs[96 + h*6 + j];
            else if (m == 1) th = py  * freqs[96 + h*6 + j];
            else if (m == 2) th = pxo * freqs[h*6 + j];
            else if (m == 3) th = px  * freqs[h*6 + j];
            else             th = tm  * t_freqs[h*6 + j];
            sincosf(th, &sv, &cv);
        }
        int idxA = (lane < 30) ? lane : (lane - 30);
        int idxB = (lane < 28) ? (lane + 2) : 0;
        float cA = __shfl_sync(0xffffffffu, cv, idxA);
        float sA = __shfl_sync(0xffffffffu, sv, idxA);
        float cB = __shfl_sync(0xffffffffu, cv, idxB);
        float sB = __shfl_sync(0xffffffffu, sv, idxB);

        size_t rowoff = (size_t)wid * D_;
        #pragma unroll
        for (int which = 0; which < 2; which++) {
            const float* xr = (which == 0 ? q : k) + rowoff;
            float* so = (which == 0 ? sq : sk);

            float xa = xr[lane];
            float xb = xr[lane+32];
            float xc = (lane < 8) ? xr[lane+64] : 0.f;
            float xpa = (lane < 30) ? xr[lane+30] : xr[lane-30];
            float xpb = (lane < 28) ? xr[lane+2]  : 0.f;

            float oa = (lane < 30) ? (xa*cA - xpa*sA) : (xa*cA + xpa*sA);
            float ob = (lane < 28) ? (xb*cB + xpb*sB) : xb;
            float oc = xc;

            float ss = oa*oa + ob*ob + oc*oc;
            #pragma unroll
            for (int mm = 16; mm >= 1; mm >>= 1)
                ss += __shfl_xor_sync(0xffffffffu, ss, mm);
            float fac = fac_scale * rsqrtf(ss + 1e-6f);

            so[lane*33 + sl]      = oa*fac;
            so[(lane+32)*33 + sl] = ob*fac;
            if (lane < 8) so[(lane+64)*33 + sl] = oc*fac;
        }
    }
    __syncthreads();

    // coalesced transposed write: [bh][d][s]
    size_t obase = (size_t)bh * D_ * S_ + s0;
    for (int i = tid; i < 72*32; i += NT) {
        int d = i >> 5, sl = i & 31;
        g_qrT[obase + (size_t)d*S_ + sl] = sq[d*33 + sl];
        g_krT[obase + (size_t)d*S_ + sl] = sk[d*33 + sl];
    }
}

// ---------------------------------------------------------------------------
// Kernel 2: flash attention over the block mask.
// q-tiles 0..8 -> zeros. 9..16 causal (tiles 0..qt, diag triangular).
// 17..31: 17 full prefix tiles + diagonal-only self tile (fast path).
// stage1: 64x64 scores, 4x4 frags; stage2: O += P@V, 4x5 frags, V transposed.
// ---------------------------------------------------------------------------
__global__ void __launch_bounds__(256, 3)
attn_kernel(const float* __restrict__ v, float* __restrict__ out)
{
    int qt  = blockIdx.x;
    int bh  = blockIdx.y;
    int tid = threadIdx.x;
    float* obase = out + (size_t)bh*S_*D_;
    int q0 = qt*64;

    if (qt < 9) {
        for (int i = tid; i < 64*D_; i += NT) obase[q0*D_ + i] = 0.f;
        return;
    }

    extern __shared__ float sm[];
    float* QsT  = sm;                 // [72][64] d-major
    float* KsT  = QsT + 72*64;        // [72][64] d-major
    float* VsT  = KsT + 72*64;        // [80][68] d-major (rows 72..79 zero)
    float* Ps   = VsT + 80*LDK;       // [64][64] row-major
    float* rowm = Ps  + 64*LDP;
    float* rowl = rowm + 64;
    float* rowa = rowl + 64;
    float* srr  = rowa + 64;

    const float* vbase = v     + (size_t)bh*S_*D_;
    const float* qbase = g_qrT + (size_t)bh*D_*S_;
    const float* kbase = g_krT + (size_t)bh*D_*S_;

    // Q tile (coalesced, d-major direct), V pad rows, stats init
    for (int i = tid; i < 72*64; i += NT) {
        // i = d*64 + r
        QsT[i] = qbase[(size_t)(i >> 6)*S_ + q0 + (i & 63)];
    }
    if (tid < 64) { rowm[tid] = -1e30f; rowl[tid] = 0.f; }
    for (int i = tid; i < 8*LDK; i += NT) VsT[72*LDK + i] = 0.f;

    float acc[20];
    #pragma unroll
    for (int i = 0; i < 20; i++) acc[i] = 0.f;

    int ty = tid >> 4, tx = tid & 15;
    int r0  = ty*4;        // rows (both stages)
    int c0  = tx*4;        // stage1 cols
    int c02 = tx*5;        // stage2 cols (over 80 padded)

    bool causal = (qt <= 16);
    int nkt = causal ? (qt + 1) : 18;
    const float L2E = 1.4426950408889634f;

    for (int kti = 0; kti < nkt; kti++) {
        bool diagC = causal && (kti == qt);
        bool diagS = (!causal && kti == 17);
        int  kt    = diagS ? qt : kti;
        int  k0    = kt*64;

        __syncthreads();   // previous stage reads of KsT/VsT done
        for (int i = tid; i < 72*64; i += NT)
            KsT[i] = kbase[(size_t)(i >> 6)*S_ + k0 + (i & 63)];
        for (int i = tid; i < 64*72; i += NT) {
            int r = i / 72, d = i - r*72;
            VsT[d*LDK + r] = vbase[(size_t)(k0 + r)*D_ + d];
        }
        __syncthreads();

        if (diagS) {
            // ---- fast path: only the diagonal of this tile is unmasked ----
            if (tid < 64) {
                float s_ = 0.f;
                #pragma unroll 8
                for (int d = 0; d < D_; d++)
                    s_ = fmaf(QsT[d*64 + tid], KsT[d*64 + tid], s_);
                float mo = rowm[tid];
                float mn = fmaxf(mo, s_);
                float a  = exp2f((mo - mn)*L2E);
                float p  = exp2f((s_ - mn)*L2E);
                rowa[tid] = a;
                srr[tid]  = p;
                rowm[tid] = mn;
                rowl[tid] = rowl[tid]*a + p;
            }
            __syncthreads();
            #pragma unroll
            for (int i = 0; i < 4; i++) {
                float a = rowa[r0+i];
                float p = srr[r0+i];
                #pragma unroll
                for (int j = 0; j < 5; j++)
                    acc[i*5+j] = acc[i*5+j]*a + p * VsT[(c02+j)*LDK + (r0+i)];
            }
            continue;
        }

        // ---- stage 1: S = Q @ K^T ----
        float sf[4][4];
        #pragma unroll
        for (int i = 0; i < 4; i++)
            #pragma unroll
            for (int j = 0; j < 4; j++) sf[i][j] = 0.f;

        #pragma unroll 4
        for (int kk = 0; kk < D_; kk++) {
            float4 qv = *(const float4*)(QsT + kk*64 + r0);
            float4 kv = *(const float4*)(KsT + kk*64 + c0);
            float qq[4] = {qv.x, qv.y, qv.z, qv.w};
            float kw[4] = {kv.x, kv.y, kv.z, kv.w};
            #pragma unroll
            for (int i = 0; i < 4; i++)
                #pragma unroll
                for (int j = 0; j < 4; j++)
                    sf[i][j] = fmaf(qq[i], kw[j], sf[i][j]);
        }

        if (diagC) {
            #pragma unroll
            for (int i = 0; i < 4; i++)
                #pragma unroll
                for (int j = 0; j < 4; j++)
                    if (c0 + j > r0 + i) sf[i][j] = -1e30f;
        }

        // ---- online softmax ----
        float mo[4], mn[4], rs[4];
        #pragma unroll
        for (int i = 0; i < 4; i++) {
            float m0 = fmaxf(fmaxf(sf[i][0], sf[i][1]), fmaxf(sf[i][2], sf[i][3]));
            #pragma unroll
            for (int mm = 8; mm >= 1; mm >>= 1)
                m0 = fmaxf(m0, __shfl_xor_sync(0xffffffffu, m0, mm));
            mo[i] = rowm[r0+i];
            mn[i] = fmaxf(mo[i], m0);
        }
        #pragma unroll
        for (int i = 0; i < 4; i++) {
            float p0 = exp2f((sf[i][0]-mn[i])*L2E);
            float p1 = exp2f((sf[i][1]-mn[i])*L2E);
            float p2 = exp2f((sf[i][2]-mn[i])*L2E);
            float p3 = exp2f((sf[i][3]-mn[i])*L2E);
            rs[i] = (p0+p1) + (p2+p3);
            *(float4*)(Ps + (r0+i)*LDP + c0) = make_float4(p0,p1,p2,p3);
        }
        #pragma unroll
        for (int i = 0; i < 4; i++) {
            float r_ = rs[i];
            #pragma unroll
            for (int mm = 8; mm >= 1; mm >>= 1)
                r_ += __shfl_xor_sync(0xffffffffu, r_, mm);
            rs[i] = r_;
        }
        __syncwarp();
        if (tx == 0) {
            #pragma unroll
            for (int i = 0; i < 4; i++) {
                float a = exp2f((mo[i]-mn[i])*L2E);
                rowa[r0+i] = a;
                rowm[r0+i] = mn[i];
                rowl[r0+i] = rowl[r0+i]*a + rs[i];
            }
        }
        __syncthreads();

        // ---- stage 2: O = O*alpha + P @ V  (4x5 frags, vectorized) ----
        #pragma unroll
        for (int i = 0; i < 4; i++) {
            float a = rowa[r0+i];
            #pragma unroll
            for (int j = 0; j < 5; j++) acc[i*5+j] *= a;
        }

        #pragma unroll 2
        for (int k4 = 0; k4 < 64; k4 += 4) {
            float4 pv[4];
            #pragma unroll
            for (int i = 0; i < 4; i++)
                pv[i] = *(const float4*)(Ps + (r0+i)*LDP + k4);
            #pragma unroll
            for (int j = 0; j < 5; j++) {
                float4 vv = *(const float4*)(VsT + (c02+j)*LDK + k4);
                #pragma unroll
                for (int i = 0; i < 4; i++) {
                    acc[i*5+j] = fmaf(pv[i].x, vv.x, acc[i*5+j]);
                    acc[i*5+j] = fmaf(pv[i].y, vv.y, acc[i*5+j]);
                    acc[i*5+j] = fmaf(pv[i].z, vv.z, acc[i*5+j]);
                    acc[i*5+j] = fmaf(pv[i].w, vv.w, acc[i*5+j]);
                }
            }
        }
    }

    __syncthreads();
    #pragma unroll
    for (int i = 0; i < 4; i++) {
        float invl = 1.f / rowl[r0+i];
        #pragma unroll
        for (int j = 0; j < 5; j++) {
            int c = c02 + j;
            if (c < D_)
                obase[(size_t)(q0 + r0 + i)*D_ + c] = acc[i*5+j]*invl;
        }
    }
}

extern "C" void kernel_launch(void* const* d_in, const int* in_sizes, int n_in,
                              void* d_out, int out_size)
{
    const float* q        = (const float*)d_in[0];
    const float* k        = (const float*)d_in[1];
    const float* v        = (const float*)d_in[2];
    const float* pos      = (const float*)d_in[3];
    const float* pos_orig = (const float*)d_in[4];
    const float* tim      = (const float*)d_in[5];
    const float* freqs    = (const float*)d_in[6];
    const float* t_freqs  = (const float*)d_in[7];
    const float* scale    = (const float*)d_in[8];
    float* out = (float*)d_out;

    const int smem_bytes = (72*64 + 72*64 + 80*LDK + 64*LDP + 256) * 4;  // 76032 B
    cudaFuncSetAttribute(attn_kernel, cudaFuncAttributeMaxDynamicSharedMemorySize, smem_bytes);

    prep_kernel<<<BHS_/32, NT>>>(q, k, pos, pos_orig, tim, freqs, t_freqs, scale);

    dim3 grid(S_/64, B_*H_);
    attn_kernel<<<grid, NT, smem_bytes>>>(v, out);
}

// round 5
// speedup vs baseline: 2.1508x; 1.3192x over previous
#include <cuda_runtime.h>
#include <cstdint>
#include <math.h>

#define B_ 2
#define H_ 16
#define S_ 2048
#define D_ 72
#define BHS_ (B_*H_*S_)
#define L2E 1.4426950408889634f

#define NT 256
#define LDKs 68
#define LDPs 64

// TMEM column offsets
#define TQ  0
#define TSP 80
#define TO  144

// tcgen05 only legal in the sm_103a-specific device pass
#if !defined(__CUDA_ARCH__) || defined(__CUDA_ARCH_FEAT_SM103_ALL)
#define TC_OK 1
#else
#define TC_OK 0
#endif

__device__ float g_qr [BHS_*D_];   // row-major (TC path)
__device__ float g_kr [BHS_*D_];
__device__ float g_qrT[BHS_*D_];   // d-major per head (SIMT fallback)
__device__ float g_krT[BHS_*D_];
__device__ int   g_use_tc;

// ---------------- PTX helpers ----------------
__device__ __forceinline__ uint32_t s2u(const void* p){ uint32_t a;
  asm("{ .reg .u64 t; cvta.to.shared.u64 t, %1; cvt.u32.u64 %0, t; }" : "=r"(a) : "l"(p)); return a; }
__device__ __forceinline__ float ex2f_(float x){ float y;
  asm("ex2.approx.ftz.f32 %0, %1;" : "=f"(y) : "f"(x)); return y; }
__device__ __forceinline__ uint32_t f2tf(float x){ uint32_t u;
  asm("cvt.rna.tf32.f32 %0, %1;" : "=r"(u) : "f"(x)); return u; }

#if TC_OK
__device__ __forceinline__ uint32_t elect1(){ uint32_t e;
  asm volatile("{\n\t.reg .pred p;\n\telect.sync _|p, 0xFFFFFFFF;\n\tselp.b32 %0, 1, 0, p;\n\t}" : "=r"(e)); return e; }
__device__ __forceinline__ uint64_t mkdesc(uint32_t addr){
  const uint64_t base = (uint64_t(2)<<61) | (uint64_t(1)<<46) | (uint64_t(64)<<32) | (uint64_t(1)<<16);
  return base | ((uint64_t)(addr >> 4) & 0x3FFF);
}
__device__ __forceinline__ void mma_tf32_ts(uint32_t d, uint32_t a, uint64_t bd, uint32_t idesc, uint32_t en){
  asm volatile("{\n\t.reg .pred p;\n\tsetp.ne.u32 p, %4, 0;\n\t"
    "tcgen05.mma.cta_group::1.kind::tf32 [%0], [%1], %2, %3, {%5,%5,%5,%5}, p;\n\t}"
    :: "r"(d), "r"(a), "l"(bd), "r"(idesc), "r"(en), "r"(0u) : "memory");
}

#define TC_ALLOC(sa,n)  asm volatile("tcgen05.alloc.cta_group::1.sync.aligned.shared::cta.b32 [%0], %1;" :: "r"(sa), "r"(n) : "memory")
#define TC_DEALLOC(tb,n) asm volatile("tcgen05.dealloc.cta_group::1.sync.aligned.b32 %0, %1;" :: "r"(tb), "r"(n))
#define TC_RELINQ()     asm volatile("tcgen05.relinquish_alloc_permit.cta_group::1.sync.aligned;")
#define TC_COMMIT(mb)   asm volatile("tcgen05.commit.cta_group::1.mbarrier::arrive::one.shared::cluster.b64 [%0];" :: "r"(mb) : "memory")
#define TC_WAIT_LD()    asm volatile("tcgen05.wait::ld.sync.aligned;" ::: "memory")
#define TC_WAIT_ST()    asm volatile("tcgen05.wait::st.sync.aligned;" ::: "memory")
#define TC_FENCE_B()    asm volatile("tcgen05.fence::before_thread_sync;" ::: "memory")
#define TC_FENCE_A()    asm volatile("tcgen05.fence::after_thread_sync;" ::: "memory")
#define FENCE_ASYNC()   asm volatile("fence.proxy.async.shared::cta;" ::: "memory")
#define MB_INIT(mb,c)   asm volatile("mbarrier.init.shared.b64 [%0], %1;" :: "r"(mb), "r"(c) : "memory")

#define MB_WAIT(mbar, par) do { \
  uint32_t _m = (mbar); uint32_t _p = (par); uint32_t _d; \
  asm volatile("{\n\t.reg .pred p;\n\t" \
    "mbarrier.try_wait.parity.acquire.cta.shared::cta.b64 p, [%1], %2;\n\t" \
    "selp.b32 %0, 1, 0, p;\n\t}" : "=r"(_d) : "r"(_m), "r"(_p) : "memory"); \
  if (!_d) { \
    asm volatile("{\n\t.reg .pred P1;\n\t" \
      "WL_%=:\n\t" \
      "mbarrier.try_wait.parity.acquire.cta.shared::cta.b64 P1, [%0], %1, 0x989680;\n\t" \
      "@P1 bra.uni WD_%=;\n\tbra.uni WL_%=;\n\tWD_%=:\n\t}" \
      :: "r"(_m), "r"(_p) : "memory"); \
  } \
} while(0)

#define LDTM_X32(r,a) \
  asm volatile("tcgen05.ld.sync.aligned.32x32b.x32.b32 " \
    "{%0,%1,%2,%3,%4,%5,%6,%7,%8,%9,%10,%11,%12,%13,%14,%15," \
    "%16,%17,%18,%19,%20,%21,%22,%23,%24,%25,%26,%27,%28,%29,%30,%31}, [%32];" \
    : "=r"((r)[0]),"=r"((r)[1]),"=r"((r)[2]),"=r"((r)[3]),"=r"((r)[4]),"=r"((r)[5]),"=r"((r)[6]),"=r"((r)[7]), \
      "=r"((r)[8]),"=r"((r)[9]),"=r"((r)[10]),"=r"((r)[11]),"=r"((r)[12]),"=r"((r)[13]),"=r"((r)[14]),"=r"((r)[15]), \
      "=r"((r)[16]),"=r"((r)[17]),"=r"((r)[18]),"=r"((r)[19]),"=r"((r)[20]),"=r"((r)[21]),"=r"((r)[22]),"=r"((r)[23]), \
      "=r"((r)[24]),"=r"((r)[25]),"=r"((r)[26]),"=r"((r)[27]),"=r"((r)[28]),"=r"((r)[29]),"=r"((r)[30]),"=r"((r)[31]) \
    : "r"(a))

#define LDTM_X8(r,a) \
  asm volatile("tcgen05.ld.sync.aligned.32x32b.x8.b32 {%0,%1,%2,%3,%4,%5,%6,%7}, [%8];" \
    : "=r"((r)[0]),"=r"((r)[1]),"=r"((r)[2]),"=r"((r)[3]),"=r"((r)[4]),"=r"((r)[5]),"=r"((r)[6]),"=r"((r)[7]) \
    : "r"(a))

#define STTM_X32(a,r) \
  asm volatile("tcgen05.st.sync.aligned.32x32b.x32.b32 [%0], " \
    "{%1,%2,%3,%4,%5,%6,%7,%8,%9,%10,%11,%12,%13,%14,%15,%16," \
    "%17,%18,%19,%20,%21,%22,%23,%24,%25,%26,%27,%28,%29,%30,%31,%32};" \
    :: "r"(a), \
       "r"((r)[0]),"r"((r)[1]),"r"((r)[2]),"r"((r)[3]),"r"((r)[4]),"r"((r)[5]),"r"((r)[6]),"r"((r)[7]), \
       "r"((r)[8]),"r"((r)[9]),"r"((r)[10]),"r"((r)[11]),"r"((r)[12]),"r"((r)[13]),"r"((r)[14]),"r"((r)[15]), \
       "r"((r)[16]),"r"((r)[17]),"r"((r)[18]),"r"((r)[19]),"r"((r)[20]),"r"((r)[21]),"r"((r)[22]),"r"((r)[23]), \
       "r"((r)[24]),"r"((r)[25]),"r"((r)[26]),"r"((r)[27]),"r"((r)[28]),"r"((r)[29]),"r"((r)[30]),"r"((r)[31]) \
    : "memory")

#define STTM_X8(a,r) \
  asm volatile("tcgen05.st.sync.aligned.32x32b.x8.b32 [%0], {%1,%2,%3,%4,%5,%6,%7,%8};" \
    :: "r"(a), "r"((r)[0]),"r"((r)[1]),"r"((r)[2]),"r"((r)[3]),"r"((r)[4]),"r"((r)[5]),"r"((r)[6]),"r"((r)[7]) \
    : "memory")
#endif // TC_OK

// idesc: f32 D (bit4), tf32 A (2<<7), tf32 B (2<<10), N>>3 @17, M>>4 @24
#define IDESC_QK (0x10u | (2u<<7) | (2u<<10) | (8u<<17) | (8u<<24))   // N=64
#define IDESC_PV (0x10u | (2u<<7) | (2u<<10) | (9u<<17) | (8u<<24))   // N=72

#define SWZ(x) ((x) ^ (((x)>>3) & 0x70))

// ---------------------------------------------------------------------------
// Kernel 1: RoPE + L2 normalize. Writes row-major (TC) AND d-major (SIMT).
// ---------------------------------------------------------------------------
__global__ void prep_kernel(const float* __restrict__ q, const float* __restrict__ k,
                            const float* __restrict__ pos, const float* __restrict__ pos_orig,
                            const float* __restrict__ tim, const float* __restrict__ freqs,
                            const float* __restrict__ t_freqs, const float* __restrict__ scale)
{
    __shared__ float sq[72*33];
    __shared__ float sk[72*33];

    int tid  = threadIdx.x;
    int wrp  = tid >> 5;
    int lane = tid & 31;
    int row0 = blockIdx.x * 32;
    int bh   = row0 >> 11;
    int h    = bh & (H_-1);
    int s0   = row0 & (S_-1);

    if (blockIdx.x == 0 && tid == 0) {
#if defined(__CUDA_ARCH_FEAT_SM103_ALL)
        g_use_tc = 1;
#else
        g_use_tc = 0;
#endif
    }

    float fac_scale = sqrtf(scale[h]);

    for (int r = 0; r < 4; r++) {
        int sl  = wrp*4 + r;
        int wid = row0 + sl;
        int s   = s0 + sl;
        int b   = bh >> 4;
        int bs  = b*S_ + s;

        float px  = pos[bs*2+0]*2.f - 1.f;
        float py  = pos[bs*2+1]*2.f - 1.f;
        float pxo = pos_orig[bs*2+0]*2.f - 1.f;
        float pyo = pos_orig[bs*2+1]*2.f - 1.f;
        float tm  = tim[bs];

        float cv = 1.f, sv = 0.f;
        if (lane < 30) {
            int m = lane / 6, j = lane % 6;
            float th;
            if      (m == 0) th = pyo * freqs[96 + h*6 + j];
            else if (m == 1) th = py  * freqs[96 + h*6 + j];
            else if (m == 2) th = pxo * freqs[h*6 + j];
            else if (m == 3) th = px  * freqs[h*6 + j];
            else             th = tm  * t_freqs[h*6 + j];
            sincosf(th, &sv, &cv);
        }
        int idxA = (lane < 30) ? lane : (lane - 30);
        int idxB = (lane < 28) ? (lane + 2) : 0;
        float cA = __shfl_sync(0xffffffffu, cv, idxA);
        float sA = __shfl_sync(0xffffffffu, sv, idxA);
        float cB = __shfl_sync(0xffffffffu, cv, idxB);
        float sB = __shfl_sync(0xffffffffu, sv, idxB);

        size_t rowoff = (size_t)wid * D_;
        #pragma unroll
        for (int which = 0; which < 2; which++) {
            const float* xr = (which == 0 ? q : k) + rowoff;
            float* so = (which == 0 ? sq : sk);
            float* xo = (which == 0 ? g_qr : g_kr) + rowoff;

            float xa = xr[lane];
            float xb = xr[lane+32];
            float xc = (lane < 8) ? xr[lane+64] : 0.f;
            float xpa = (lane < 30) ? xr[lane+30] : xr[lane-30];
            float xpb = (lane < 28) ? xr[lane+2]  : 0.f;

            float oa = (lane < 30) ? (xa*cA - xpa*sA) : (xa*cA + xpa*sA);
            float ob = (lane < 28) ? (xb*cB + xpb*sB) : xb;
            float oc = xc;

            float ss = oa*oa + ob*ob + oc*oc;
            #pragma unroll
            for (int mm = 16; mm >= 1; mm >>= 1)
                ss += __shfl_xor_sync(0xffffffffu, ss, mm);
            float fac = fac_scale * rsqrtf(ss + 1e-6f);

            so[lane*33 + sl]      = oa*fac;
            so[(lane+32)*33 + sl] = ob*fac;
            if (lane < 8) so[(lane+64)*33 + sl] = oc*fac;
            xo[lane]    = oa*fac;
            xo[lane+32] = ob*fac;
            if (lane < 8) xo[lane+64] = oc*fac;
        }
    }
    __syncthreads();

    size_t obase = (size_t)bh * D_ * S_ + s0;
    for (int i = tid; i < 72*32; i += NT) {
        int d = i >> 5, sl = i & 31;
        g_qrT[obase + (size_t)d*S_ + sl] = sq[d*33 + sl];
        g_krT[obase + (size_t)d*S_ + sl] = sk[d*33 + sl];
    }
}

// ---------------------------------------------------------------------------
// Kernel 2a: tcgen05 tf32 flash attention (sm_103a-specific builds only).
// ---------------------------------------------------------------------------
__global__ void __launch_bounds__(256)
attn_tc(const float* __restrict__ v, float* __restrict__ out)
{
#if TC_OK
    int qt  = blockIdx.x;
    int bh  = blockIdx.y;
    int tid = threadIdx.x;
    int q0  = qt*128;
    float* obase = out + (size_t)bh*S_*D_;

    if (qt < 4) {
        for (int i = tid; i < 128*D_; i += 256) obase[q0*D_ + i] = 0.f;
        return;
    }

    __shared__ __align__(1024) char Ksw[24576];   // 64r x 96c fp32, SW128 atoms (8x3)
    __shared__ __align__(1024) char Vsw[18432];   // 72r x 64c fp32, SW128 atoms (9x2)
    __shared__ __align__(16) uint32_t s_tmem[4];
    __shared__ __align__(16) uint64_t s_mbar[2];

    uint32_t kaddr = s2u(Ksw), vaddr = s2u(Vsw);
    uint32_t mb1 = s2u(&s_mbar[0]), mb2 = s2u(&s_mbar[1]);
    int wid = tid >> 5;

    if (wid == 4) TC_ALLOC(s2u(s_tmem), 256);
    if (tid == 0) { MB_INIT(mb1, 1); MB_INIT(mb2, 1); }
    __syncthreads();
    uint32_t tb;
    asm volatile("ld.shared.b32 %0, [%1];" : "=r"(tb) : "r"(s2u(s_tmem)));

    const float* qbase = g_qr + (size_t)bh*S_*D_;
    const float* kbase = g_kr + (size_t)bh*S_*D_;
    const float* vbase = v    + (size_t)bh*S_*D_;

    int q    = q0 + tid;
    int qeff = (q < 576) ? -1 : ((q < 1088) ? q : 0x7fffffff);
    float sum = 0.f, selfp = 0.f;

    if (tid < 128) {
        uint32_t woff = (uint32_t)(tid >> 5) << 21;
        const float* qp = qbase + (size_t)q*D_;
        uint32_t r32[32];
        #pragma unroll
        for (int j = 0; j < 32; j++) r32[j] = f2tf(qp[j]);
        STTM_X32(tb + TQ + woff, r32);
        #pragma unroll
        for (int j = 0; j < 32; j++) r32[j] = f2tf(qp[32+j]);
        STTM_X32(tb + TQ + 32 + woff, r32);
        uint32_t r8[8];
        #pragma unroll
        for (int j = 0; j < 8; j++) r8[j] = f2tf(qp[64+j]);
        STTM_X8(tb + TQ + 64 + woff, r8);
        TC_WAIT_ST();
        TC_FENCE_B();

        if (q >= 1088) {
            const float* kp = kbase + (size_t)q*D_;
            float sdot = 0.f;
            #pragma unroll 8
            for (int d = 0; d < D_; d++) sdot = fmaf(qp[d], kp[d], sdot);
            selfp = ex2f_((sdot - 1.5f)*L2E);
            sum = selfp;
        }
    }
    __syncthreads();

    uint64_t kdesc0 = mkdesc(kaddr);
    uint64_t vdesc0 = mkdesc(vaddr);
    int ktn = (qt >= 8) ? 17 : (2*qt + 2);
    int ph1 = 0, ph2 = 0;

    for (int kt = 0; kt < ktn; kt++) {
        int k0 = kt*64;

        for (int i = tid; i < 64*D_; i += 256) {
            int r = i / D_, d = i - r*D_;
            float kvv = kbase[(size_t)(k0 + r)*D_ + d];
            uint32_t off = ((uint32_t)((r>>3) + (d>>5)*8))*1024u + (uint32_t)(r&7)*128u + (uint32_t)(d&31)*4u;
            *(uint32_t*)(Ksw + SWZ(off)) = f2tf(kvv);
            float vvv = vbase[(size_t)(k0 + r)*D_ + d];
            uint32_t vo = ((uint32_t)((d>>3) + (r>>5)*9))*1024u + (uint32_t)(d&7)*128u + (uint32_t)(r&31)*4u;
            *(uint32_t*)(Vsw + SWZ(vo)) = f2tf(vvv);
        }
        __syncthreads();

        if (wid == 4) {
            FENCE_ASYNC();
            TC_FENCE_A();
            if (elect1()) {
                #pragma unroll
                for (int s8 = 0; s8 < 9; s8++) {
                    uint64_t bd = kdesc0 + (uint64_t)((s8>>2)*512 + (s8&3)*2);
                    mma_tf32_ts(tb + TSP, tb + TQ + s8*8, bd, IDESC_QK, s8 > 0);
                }
                TC_COMMIT(mb1);
            }
        }
        MB_WAIT(mb1, ph1); ph1 ^= 1;

        if (tid < 128) {
            TC_FENCE_A();
            uint32_t woff = (uint32_t)(tid >> 5) << 21;
            uint32_t sr[32], pr[32];
            #pragma unroll
            for (int half = 0; half < 2; half++) {
                LDTM_X32(sr, tb + TSP + half*32);
                TC_WAIT_LD();
                float lsum = 0.f;
                #pragma unroll
                for (int j = 0; j < 32; j++) {
                    int kk = k0 + half*32 + j;
                    float sc = __uint_as_float(sr[j]);
                    float p  = (kk <= qeff) ? ex2f_(fmaf(sc, L2E, -1.5f*L2E)) : 0.f;
                    pr[j] = f2tf(p);
                    lsum += __uint_as_float(pr[j]);
                }
                sum += lsum;
                STTM_X32(tb + TSP + half*32 + woff, pr);
            }
            TC_WAIT_ST();
            TC_FENCE_B();
        }
        __syncthreads();

        if (wid == 4) {
            TC_FENCE_A();
            if (elect1()) {
                #pragma unroll
                for (int s8 = 0; s8 < 8; s8++) {
                    uint64_t bd = vdesc0 + (uint64_t)((s8>>2)*576 + (s8&3)*2);
                    mma_tf32_ts(tb + TO, tb + TSP + s8*8, bd, IDESC_PV, (kt > 0) || (s8 > 0));
                }
                TC_COMMIT(mb2);
            }
        }
        MB_WAIT(mb2, ph2); ph2 ^= 1;
    }

    if (tid < 128) {
        TC_FENCE_A();
        uint32_t o1[32], o2[32], o3[8];
        LDTM_X32(o1, tb + TO);
        LDTM_X32(o2, tb + TO + 32);
        LDTM_X8 (o3, tb + TO + 64);
        TC_WAIT_LD();

        float* op = obase + (size_t)q*D_;
        if (q < 576) {
            #pragma unroll
            for (int d = 0; d < D_; d++) op[d] = 0.f;
        } else {
            float inv = 1.f / sum;
            const float* vp = vbase + (size_t)q*D_;
            #pragma unroll
            for (int d = 0; d < 32; d++) op[d]    = (__uint_as_float(o1[d]) + selfp*vp[d])    * inv;
            #pragma unroll
            for (int d = 0; d < 32; d++) op[32+d] = (__uint_as_float(o2[d]) + selfp*vp[32+d]) * inv;
            #pragma unroll
            for (int d = 0; d < 8; d++)  op[64+d] = (__uint_as_float(o3[d]) + selfp*vp[64+d]) * inv;
        }
    }
    __syncthreads();
    if (wid == 4) {
        TC_RELINQ();
        TC_DEALLOC(tb, 256);
    }
#endif
}

// ---------------------------------------------------------------------------
// Kernel 2b: SIMT fallback (the known-good R3 kernel), runs iff g_use_tc==0.
// ---------------------------------------------------------------------------
__global__ void __launch_bounds__(256, 3)
attn_simt(const float* __restrict__ v, float* __restrict__ out)
{
    if (g_use_tc) return;

    int qt  = blockIdx.x;
    int bh  = blockIdx.y;
    int tid = threadIdx.x;
    float* obase = out + (size_t)bh*S_*D_;
    int q0 = qt*64;

    if (qt < 9) {
        for (int i = tid; i < 64*D_; i += NT) obase[q0*D_ + i] = 0.f;
        return;
    }

    extern __shared__ float smf[];
    float* QsT  = smf;
    float* KsT  = QsT + 72*64;
    float* VsT  = KsT + 72*64;
    float* Ps   = VsT + 80*LDKs;
    float* rowm = Ps  + 64*LDPs;
    float* rowl = rowm + 64;
    float* rowa = rowl + 64;
    float* srr  = rowa + 64;

    const float* vbase = v     + (size_t)bh*S_*D_;
    const float* qbase = g_qrT + (size_t)bh*D_*S_;
    const float* kbase = g_krT + (size_t)bh*D_*S_;

    for (int i = tid; i < 72*64; i += NT)
        QsT[i] = qbase[(size_t)(i >> 6)*S_ + q0 + (i & 63)];
    if (tid < 64) { rowm[tid] = -1e30f; rowl[tid] = 0.f; }
    for (int i = tid; i < 8*LDKs; i += NT) VsT[72*LDKs + i] = 0.f;

    float acc[20];
    #pragma unroll
    for (int i = 0; i < 20; i++) acc[i] = 0.f;

    int ty = tid >> 4, tx = tid & 15;
    int r0  = ty*4, c0 = tx*4, c02 = tx*5;

    bool causal = (qt <= 16);
    int nkt = causal ? (qt + 1) : 18;

    for (int kti = 0; kti < nkt; kti++) {
        bool diagC = causal && (kti == qt);
        bool diagS = (!causal && kti == 17);
        int  kt    = diagS ? qt : kti;
        int  k0    = kt*64;

        __syncthreads();
        for (int i = tid; i < 72*64; i += NT)
            KsT[i] = kbase[(size_t)(i >> 6)*S_ + k0 + (i & 63)];
        for (int i = tid; i < 64*72; i += NT) {
            int r = i / 72, d = i - r*72;
            VsT[d*LDKs + r] = vbase[(size_t)(k0 + r)*D_ + d];
        }
        __syncthreads();

        if (diagS) {
            if (tid < 64) {
                float s_ = 0.f;
                #pragma unroll 8
                for (int d = 0; d < D_; d++)
                    s_ = fmaf(QsT[d*64 + tid], KsT[d*64 + tid], s_);
                float mo = rowm[tid];
                float mn = fmaxf(mo, s_);
                float a  = exp2f((mo - mn)*L2E);
                float p  = exp2f((s_ - mn)*L2E);
                rowa[tid] = a; srr[tid] = p; rowm[tid] = mn;
                rowl[tid] = rowl[tid]*a + p;
            }
            __syncthreads();
            #pragma unroll
            for (int i = 0; i < 4; i++) {
                float a = rowa[r0+i], p = srr[r0+i];
                #pragma unroll
                for (int j = 0; j < 5; j++)
                    acc[i*5+j] = acc[i*5+j]*a + p * VsT[(c02+j)*LDKs + (r0+i)];
            }
            continue;
        }

        float sf[4][4];
        #pragma unroll
        for (int i = 0; i < 4; i++)
            #pragma unroll
            for (int j = 0; j < 4; j++) sf[i][j] = 0.f;

        #pragma unroll 4
        for (int kk = 0; kk < D_; kk++) {
            float4 qv = *(const float4*)(QsT + kk*64 + r0);
            float4 kv = *(const float4*)(KsT + kk*64 + c0);
            float qq[4] = {qv.x, qv.y, qv.z, qv.w};
            float kw[4] = {kv.x, kv.y, kv.z, kv.w};
            #pragma unroll
            for (int i = 0; i < 4; i++)
                #pragma unroll
                for (int j = 0; j < 4; j++)
                    sf[i][j] = fmaf(qq[i], kw[j], sf[i][j]);
        }

        if (diagC) {
            #pragma unroll
            for (int i = 0; i < 4; i++)
                #pragma unroll
                for (int j = 0; j < 4; j++)
                    if (c0 + j > r0 + i) sf[i][j] = -1e30f;
        }

        float mo[4], mn[4], rs[4];
        #pragma unroll
        for (int i = 0; i < 4; i++) {
            float m0 = fmaxf(fmaxf(sf[i][0], sf[i][1]), fmaxf(sf[i][2], sf[i][3]));
            #pragma unroll
            for (int mm = 8; mm >= 1; mm >>= 1)
                m0 = fmaxf(m0, __shfl_xor_sync(0xffffffffu, m0, mm));
            mo[i] = rowm[r0+i];
            mn[i] = fmaxf(mo[i], m0);
        }
        #pragma unroll
        for (int i = 0; i < 4; i++) {
            float p0 = exp2f((sf[i][0]-mn[i])*L2E);
            float p1 = exp2f((sf[i][1]-mn[i])*L2E);
            float p2 = exp2f((sf[i][2]-mn[i])*L2E);
            float p3 = exp2f((sf[i][3]-mn[i])*L2E);
            rs[i] = (p0+p1) + (p2+p3);
            *(float4*)(Ps + (r0+i)*LDPs + c0) = make_float4(p0,p1,p2,p3);
        }
        #pragma unroll
        for (int i = 0; i < 4; i++) {
            float r_ = rs[i];
            #pragma unroll
            for (int mm = 8; mm >= 1; mm >>= 1)
                r_ += __shfl_xor_sync(0xffffffffu, r_, mm);
            rs[i] = r_;
        }
        __syncwarp();
        if (tx == 0) {
            #pragma unroll
            for (int i = 0; i < 4; i++) {
                float a = exp2f((mo[i]-mn[i])*L2E);
                rowa[r0+i] = a; rowm[r0+i] = mn[i];
                rowl[r0+i] = rowl[r0+i]*a + rs[i];
            }
        }
        __syncthreads();

        #pragma unroll
        for (int i = 0; i < 4; i++) {
            float a = rowa[r0+i];
            #pragma unroll
            for (int j = 0; j < 5; j++) acc[i*5+j] *= a;
        }

        #pragma unroll 2
        for (int k4 = 0; k4 < 64; k4 += 4) {
            float4 pv[4];
            #pragma unroll
            for (int i = 0; i < 4; i++)
                pv[i] = *(const float4*)(Ps + (r0+i)*LDPs + k4);
            #pragma unroll
            for (int j = 0; j < 5; j++) {
                float4 vv = *(const float4*)(VsT + (c02+j)*LDKs + k4);
                #pragma unroll
                for (int i = 0; i < 4; i++) {
                    acc[i*5+j] = fmaf(pv[i].x, vv.x, acc[i*5+j]);
                    acc[i*5+j] = fmaf(pv[i].y, vv.y, acc[i*5+j]);
                    acc[i*5+j] = fmaf(pv[i].z, vv.z, acc[i*5+j]);
                    acc[i*5+j] = fmaf(pv[i].w, vv.w, acc[i*5+j]);
                }
            }
        }
    }

    __syncthreads();
    #pragma unroll
    for (int i = 0; i < 4; i++) {
        float invl = 1.f / rowl[r0+i];
        #pragma unroll
        for (int j = 0; j < 5; j++) {
            int c = c02 + j;
            if (c < D_)
                obase[(size_t)(q0 + r0 + i)*D_ + c] = acc[i*5+j]*invl;
        }
    }
}

extern "C" void kernel_launch(void* const* d_in, const int* in_sizes, int n_in,
                              void* d_out, int out_size)
{
    const float* q        = (const float*)d_in[0];
    const float* k        = (const float*)d_in[1];
    const float* v        = (const float*)d_in[2];
    const float* pos      = (const float*)d_in[3];
    const float* pos_orig = (const float*)d_in[4];
    const float* tim      = (const float*)d_in[5];
    const float* freqs    = (const float*)d_in[6];
    const float* t_freqs  = (const float*)d_in[7];
    const float* scale    = (const float*)d_in[8];
    float* out = (float*)d_out;

    const int smem_simt = (72*64 + 72*64 + 80*LDKs + 64*LDPs + 256) * 4;
    cudaFuncSetAttribute(attn_simt, cudaFuncAttributeMaxDynamicSharedMemorySize, smem_simt);

    prep_kernel<<<BHS_/32, NT>>>(q, k, pos, pos_orig, tim, freqs, t_freqs, scale);

    dim3 gtc(S_/128, B_*H_);
    attn_tc<<<gtc, 256>>>(v, out);

    dim3 gsi(S_/64, B_*H_);
    attn_simt<<<gsi, NT, smem_simt>>>(v, out);
}

// round 6
// speedup vs baseline: 6.6197x; 3.0778x over previous
#include <cuda_runtime.h>
#include <cstdint>
#include <math.h>

#define B_ 2
#define H_ 16
#define S_ 2048
#define D_ 72
#define BHS_ (B_*H_*S_)
#define L2E 1.4426950408889634f

// TMEM column offsets
#define TQ  0
#define TSP 80
#define TO  144

#define KWORDS 6144          // 24576 B per swizzled K tile (64r x 96c fp32)
#define VWORDS 4608          // 18432 B per swizzled V^T tile (72r x 64c fp32)
#define KBYTES 24576
#define TILE_BYTES 43008     // K + V per k-tile

#if !defined(__CUDA_ARCH__) || defined(__CUDA_ARCH_FEAT_SM103_ALL)
#define TC_OK 1
#else
#define TC_OK 0
#endif

__device__ float g_qr[BHS_*D_];                       // normalized q, row-major
__device__ float g_sdot[BHS_];                        // q.k self dot per row
__device__ __align__(1024) uint32_t g_ksw[32*32*KWORDS];  // pre-swizzled tf32 K tiles
__device__ __align__(1024) uint32_t g_vsw[32*32*VWORDS];  // pre-swizzled tf32 V^T tiles

// ---------------- PTX helpers ----------------
__device__ __forceinline__ uint32_t s2u(const void* p){ uint32_t a;
  asm("{ .reg .u64 t; cvta.to.shared.u64 t, %1; cvt.u32.u64 %0, t; }" : "=r"(a) : "l"(p)); return a; }
__device__ __forceinline__ float ex2f_(float x){ float y;
  asm("ex2.approx.ftz.f32 %0, %1;" : "=f"(y) : "f"(x)); return y; }
__device__ __forceinline__ uint32_t f2tf(float x){ uint32_t u;
  asm("cvt.rna.tf32.f32 %0, %1;" : "=r"(u) : "f"(x)); return u; }

#define SWZ(x) ((x) ^ (((x)>>3) & 0x70))

#if TC_OK
__device__ __forceinline__ uint32_t elect1(){ uint32_t e;
  asm volatile("{\n\t.reg .pred p;\n\telect.sync _|p, 0xFFFFFFFF;\n\tselp.b32 %0, 1, 0, p;\n\t}" : "=r"(e)); return e; }
__device__ __forceinline__ uint64_t mkdesc(uint32_t addr){
  const uint64_t base = (uint64_t(2)<<61) | (uint64_t(1)<<46) | (uint64_t(64)<<32) | (uint64_t(1)<<16);
  return base | ((uint64_t)(addr >> 4) & 0x3FFF);
}
__device__ __forceinline__ void mma_tf32_ts(uint32_t d, uint32_t a, uint64_t bd, uint32_t idesc, uint32_t en){
  asm volatile("{\n\t.reg .pred p;\n\tsetp.ne.u32 p, %4, 0;\n\t"
    "tcgen05.mma.cta_group::1.kind::tf32 [%0], [%1], %2, %3, {%5,%5,%5,%5}, p;\n\t}"
    :: "r"(d), "r"(a), "l"(bd), "r"(idesc), "r"(en), "r"(0u) : "memory");
}
__device__ __forceinline__ void bulk_g2s(uint32_t dst, const void* src, uint32_t bytes, uint32_t mbar){
  asm volatile("cp.async.bulk.shared::cluster.global.mbarrier::complete_tx::bytes [%0], [%1], %2, [%3];"
    :: "r"(dst), "l"(src), "r"(bytes), "r"(mbar) : "memory");
}

#define TC_ALLOC(sa,n)  asm volatile("tcgen05.alloc.cta_group::1.sync.aligned.shared::cta.b32 [%0], %1;" :: "r"(sa), "r"(n) : "memory")
#define TC_DEALLOC(tb,n) asm volatile("tcgen05.dealloc.cta_group::1.sync.aligned.b32 %0, %1;" :: "r"(tb), "r"(n))
#define TC_RELINQ()     asm volatile("tcgen05.relinquish_alloc_permit.cta_group::1.sync.aligned;")
#define TC_COMMIT(mb)   asm volatile("tcgen05.commit.cta_group::1.mbarrier::arrive::one.shared::cluster.b64 [%0];" :: "r"(mb) : "memory")
#define TC_WAIT_LD()    asm volatile("tcgen05.wait::ld.sync.aligned;" ::: "memory")
#define TC_WAIT_ST()    asm volatile("tcgen05.wait::st.sync.aligned;" ::: "memory")
#define TC_FENCE_B()    asm volatile("tcgen05.fence::before_thread_sync;" ::: "memory")
#define TC_FENCE_A()    asm volatile("tcgen05.fence::after_thread_sync;" ::: "memory")
#define MB_INIT(mb,c)   asm volatile("mbarrier.init.shared.b64 [%0], %1;" :: "r"(mb), "r"(c) : "memory")
#define MB_EXPECT_TX(mb,n) asm volatile("mbarrier.arrive.expect_tx.shared.b64 _, [%0], %1;" :: "r"(mb), "r"(n) : "memory")

#define MB_WAIT(mbar, par) do { \
  uint32_t _m = (mbar); uint32_t _p = (par); uint32_t _d; \
  asm volatile("{\n\t.reg .pred p;\n\t" \
    "mbarrier.try_wait.parity.acquire.cta.shared::cta.b64 p, [%1], %2;\n\t" \
    "selp.b32 %0, 1, 0, p;\n\t}" : "=r"(_d) : "r"(_m), "r"(_p) : "memory"); \
  if (!_d) { \
    asm volatile("{\n\t.reg .pred P1;\n\t" \
      "WL_%=:\n\t" \
      "mbarrier.try_wait.parity.acquire.cta.shared::cta.b64 P1, [%0], %1, 0x989680;\n\t" \
      "@P1 bra.uni WD_%=;\n\tbra.uni WL_%=;\n\tWD_%=:\n\t}" \
      :: "r"(_m), "r"(_p) : "memory"); \
  } \
} while(0)

#define LDTM_X32(r,a) \
  asm volatile("tcgen05.ld.sync.aligned.32x32b.x32.b32 " \
    "{%0,%1,%2,%3,%4,%5,%6,%7,%8,%9,%10,%11,%12,%13,%14,%15," \
    "%16,%17,%18,%19,%20,%21,%22,%23,%24,%25,%26,%27,%28,%29,%30,%31}, [%32];" \
    : "=r"((r)[0]),"=r"((r)[1]),"=r"((r)[2]),"=r"((r)[3]),"=r"((r)[4]),"=r"((r)[5]),"=r"((r)[6]),"=r"((r)[7]), \
      "=r"((r)[8]),"=r"((r)[9]),"=r"((r)[10]),"=r"((r)[11]),"=r"((r)[12]),"=r"((r)[13]),"=r"((r)[14]),"=r"((r)[15]), \
      "=r"((r)[16]),"=r"((r)[17]),"=r"((r)[18]),"=r"((r)[19]),"=r"((r)[20]),"=r"((r)[21]),"=r"((r)[22]),"=r"((r)[23]), \
      "=r"((r)[24]),"=r"((r)[25]),"=r"((r)[26]),"=r"((r)[27]),"=r"((r)[28]),"=r"((r)[29]),"=r"((r)[30]),"=r"((r)[31]) \
    : "r"(a))

#define LDTM_X8(r,a) \
  asm volatile("tcgen05.ld.sync.aligned.32x32b.x8.b32 {%0,%1,%2,%3,%4,%5,%6,%7}, [%8];" \
    : "=r"((r)[0]),"=r"((r)[1]),"=r"((r)[2]),"=r"((r)[3]),"=r"((r)[4]),"=r"((r)[5]),"=r"((r)[6]),"=r"((r)[7]) \
    : "r"(a))

#define STTM_X32(a,r) \
  asm volatile("tcgen05.st.sync.aligned.32x32b.x32.b32 [%0], " \
    "{%1,%2,%3,%4,%5,%6,%7,%8,%9,%10,%11,%12,%13,%14,%15,%16," \
    "%17,%18,%19,%20,%21,%22,%23,%24,%25,%26,%27,%28,%29,%30,%31,%32};" \
    :: "r"(a), \
       "r"((r)[0]),"r"((r)[1]),"r"((r)[2]),"r"((r)[3]),"r"((r)[4]),"r"((r)[5]),"r"((r)[6]),"r"((r)[7]), \
       "r"((r)[8]),"r"((r)[9]),"r"((r)[10]),"r"((r)[11]),"r"((r)[12]),"r"((r)[13]),"r"((r)[14]),"r"((r)[15]), \
       "r"((r)[16]),"r"((r)[17]),"r"((r)[18]),"r"((r)[19]),"r"((r)[20]),"r"((r)[21]),"r"((r)[22]),"r"((r)[23]), \
       "r"((r)[24]),"r"((r)[25]),"r"((r)[26]),"r"((r)[27]),"r"((r)[28]),"r"((r)[29]),"r"((r)[30]),"r"((r)[31]) \
    : "memory")

#define STTM_X8(a,r) \
  asm volatile("tcgen05.st.sync.aligned.32x32b.x8.b32 [%0], {%1,%2,%3,%4,%5,%6,%7,%8};" \
    :: "r"(a), "r"((r)[0]),"r"((r)[1]),"r"((r)[2]),"r"((r)[3]),"r"((r)[4]),"r"((r)[5]),"r"((r)[6]),"r"((r)[7]) \
    : "memory")
#endif // TC_OK

// idesc: f32 D (bit4), tf32 A (2<<7), tf32 B (2<<10), N>>3 @17, M>>4 @24
#define IDESC_QK (0x10u | (2u<<7) | (2u<<10) | (8u<<17) | (8u<<24))   // N=64
#define IDESC_PV (0x10u | (2u<<7) | (2u<<10) | (9u<<17) | (8u<<24))   // N=72

// ---------------------------------------------------------------------------
// Kernel 1: RoPE + L2 normalize. Writes q row-major, K pre-swizzled tf32
// tiles, and the per-row self dot q.k.
// ---------------------------------------------------------------------------
__global__ void prep_kernel(const float* __restrict__ q, const float* __restrict__ k,
                            const float* __restrict__ pos, const float* __restrict__ pos_orig,
                            const float* __restrict__ tim, const float* __restrict__ freqs,
                            const float* __restrict__ t_freqs, const float* __restrict__ scale)
{
    int gid  = blockIdx.x*blockDim.x + threadIdx.x;
    int wid  = gid >> 5;
    int lane = gid & 31;
    if (wid >= BHS_) return;
    int s = wid & (S_-1);
    int h = (wid >> 11) & (H_-1);
    int b = wid >> 15;
    int bh = wid >> 11;
    int bs = b*S_ + s;

    float px  = pos[bs*2+0]*2.f - 1.f;
    float py  = pos[bs*2+1]*2.f - 1.f;
    float pxo = pos_orig[bs*2+0]*2.f - 1.f;
    float pyo = pos_orig[bs*2+1]*2.f - 1.f;
    float tm  = tim[bs];

    float cv = 1.f, sv = 0.f;
    if (lane < 30) {
        int m = lane / 6, j = lane % 6;
        float th;
        if      (m == 0) th = pyo * freqs[96 + h*6 + j];
        else if (m == 1) th = py  * freqs[96 + h*6 + j];
        else if (m == 2) th = pxo * freqs[h*6 + j];
        else if (m == 3) th = px  * freqs[h*6 + j];
        else             th = tm  * t_freqs[h*6 + j];
        sincosf(th, &sv, &cv);
    }
    int idxA = (lane < 30) ? lane : (lane - 30);
    int idxB = (lane < 28) ? (lane + 2) : 0;
    float cA = __shfl_sync(0xffffffffu, cv, idxA);
    float sA = __shfl_sync(0xffffffffu, sv, idxA);
    float cB = __shfl_sync(0xffffffffu, cv, idxB);
    float sB = __shfl_sync(0xffffffffu, sv, idxB);

    float fac_scale = sqrtf(scale[h]);
    size_t rowoff = (size_t)wid * D_;

    float qa, qb_, qc, ka, kb_, kc;
    #pragma unroll
    for (int which = 0; which < 2; which++) {
        const float* xr = (which == 0 ? q : k) + rowoff;

        float xa = xr[lane];
        float xb = xr[lane+32];
        float xc = (lane < 8) ? xr[lane+64] : 0.f;
        float xpa = (lane < 30) ? xr[lane+30] : xr[lane-30];
        float xpb = (lane < 28) ? xr[lane+2]  : 0.f;

        float oa = (lane < 30) ? (xa*cA - xpa*sA) : (xa*cA + xpa*sA);
        float ob = (lane < 28) ? (xb*cB + xpb*sB) : xb;
        float oc = xc;

        float ss = oa*oa + ob*ob + oc*oc;
        #pragma unroll
        for (int mm = 16; mm >= 1; mm >>= 1)
            ss += __shfl_xor_sync(0xffffffffu, ss, mm);
        float fac = fac_scale * rsqrtf(ss + 1e-6f);

        if (which == 0) { qa = oa*fac; qb_ = ob*fac; qc = oc*fac; }
        else            { ka = oa*fac; kb_ = ob*fac; kc = oc*fac; }
    }

    // q row-major
    g_qr[rowoff + lane]    = qa;
    g_qr[rowoff + lane+32] = qb_;
    if (lane < 8) g_qr[rowoff + lane+64] = qc;

    // K pre-swizzled tile (coalesced: fixed row -> one permuted 128B segment)
    {
        int kt = s >> 6, r = s & 63;
        uint32_t tb_ = (uint32_t)(bh*32 + kt) * KWORDS;
        uint32_t o0 = (uint32_t)(r>>3)*1024u + (uint32_t)(r&7)*128u + (uint32_t)lane*4u;
        g_ksw[tb_ + (SWZ(o0) >> 2)] = f2tf(ka);
        uint32_t o1 = (uint32_t)(8 + (r>>3))*1024u + (uint32_t)(r&7)*128u + (uint32_t)lane*4u;
        g_ksw[tb_ + (SWZ(o1) >> 2)] = f2tf(kb_);
        if (lane < 8) {
            uint32_t o2 = (uint32_t)(16 + (r>>3))*1024u + (uint32_t)(r&7)*128u + (uint32_t)lane*4u;
            g_ksw[tb_ + (SWZ(o2) >> 2)] = f2tf(kc);
        }
    }

    // self dot q.k
    float sd = qa*ka + qb_*kb_ + qc*kc;
    #pragma unroll
    for (int mm = 16; mm >= 1; mm >>= 1)
        sd += __shfl_xor_sync(0xffffffffu, sd, mm);
    if (lane == 0) g_sdot[wid] = sd;
}

// ---------------------------------------------------------------------------
// Kernel 1b: V^T pre-swizzled tf32 tiles.
// ---------------------------------------------------------------------------
__global__ void vprep_kernel(const float* __restrict__ v)
{
    __shared__ float sv[64*77];
    int bh = blockIdx.y, kt = blockIdx.x, tid = threadIdx.x;
    const float* vb = v + ((size_t)bh*S_ + kt*64)*D_;

    for (int i = tid; i < 64*D_; i += 256) {
        int r = i / D_, d = i - r*D_;
        sv[r*77 + d] = vb[i];
    }
    __syncthreads();

    uint32_t tb_ = (uint32_t)(bh*32 + kt) * VWORDS;
    for (int i = tid; i < 72*64; i += 256) {
        int d = i >> 6, r = i & 63;
        uint32_t vo = (uint32_t)((d>>3) + (r>>5)*9)*1024u + (uint32_t)(d&7)*128u + (uint32_t)(r&31)*4u;
        g_vsw[tb_ + (SWZ(vo) >> 2)] = f2tf(sv[r*77 + d]);
    }
}

// ---------------------------------------------------------------------------
// Kernel 2: tcgen05 tf32 flash attention, fixed softmax max 1.5,
// double-buffered bulk-copy pipeline over pre-swizzled tiles.
// ---------------------------------------------------------------------------
__global__ void __launch_bounds__(256, 2)
attn_tc(const float* __restrict__ v, float* __restrict__ out)
{
#if TC_OK
    int qt  = blockIdx.x;
    int bh  = blockIdx.y;
    int tid = threadIdx.x;
    int q0  = qt*128;
    float* obase = out + (size_t)bh*S_*D_;

    if (qt < 4) {
        for (int i = tid; i < 128*D_; i += 256) obase[q0*D_ + i] = 0.f;
        return;
    }

    extern __shared__ char dynsm[];
    uint32_t sbase = (s2u(dynsm) + 1023u) & ~1023u;
    uint32_t kbuf[2] = { sbase, sbase + TILE_BYTES };
    char* smraw = dynsm + (sbase - s2u(dynsm));
    float* stage1 = (float*)(smraw + TILE_BYTES);   // buf1 region: Q / V stage
    float* stage0 = (float*)(smraw);                // buf0 region: out stage

    __shared__ __align__(16) uint32_t s_tmem[4];
    __shared__ __align__(16) uint64_t s_mbar[4];
    uint32_t mbF[2] = { s2u(&s_mbar[0]), s2u(&s_mbar[1]) };
    uint32_t mb1 = s2u(&s_mbar[2]), mb2 = s2u(&s_mbar[3]);
    int wid = tid >> 5;

    if (wid == 4) TC_ALLOC(s2u(s_tmem), 256);
    if (tid == 0) { MB_INIT(mbF[0],1); MB_INIT(mbF[1],1); MB_INIT(mb1,1); MB_INIT(mb2,1); }
    __syncthreads();
    uint32_t tb;
    asm volatile("ld.shared.b32 %0, [%1];" : "=r"(tb) : "r"(s2u(s_tmem)));

    const uint32_t* ktiles = g_ksw + (size_t)(bh*32) * KWORDS;
    const uint32_t* vtiles = g_vsw + (size_t)(bh*32) * VWORDS;

    // prefetch tile 0 into buf0
    if (tid == 0) {
        MB_EXPECT_TX(mbF[0], TILE_BYTES);
        bulk_g2s(kbuf[0],          ktiles, KBYTES, mbF[0]);
        bulk_g2s(kbuf[0] + KBYTES, vtiles, TILE_BYTES - KBYTES, mbF[0]);
    }

    // stage Q (coalesced) into buf1 region
    {
        const float* qb = g_qr + ((size_t)bh*S_ + q0)*D_;
        for (int i = tid; i < 128*D_; i += 256) {
            int r = i / D_, d = i - r*D_;
            stage1[r*77 + d] = qb[i];
        }
    }
    int q    = q0 + tid;
    int qeff = (q < 576) ? -1 : ((q < 1088) ? q : 0x7fffffff);
    float sum = 0.f, selfp = 0.f;
    if (tid < 128 && q >= 1088) {
        float sd = g_sdot[(size_t)bh*S_ + q];
        selfp = ex2f_((sd - 1.5f)*L2E);
        sum = selfp;
    }
    __syncthreads();

    // Q -> TMEM
    if (tid < 128) {
        uint32_t woff = (uint32_t)(tid >> 5) << 21;
        const float* qp = stage1 + tid*77;
        uint32_t r32[32];
        #pragma unroll
        for (int j = 0; j < 32; j++) r32[j] = f2tf(qp[j]);
        STTM_X32(tb + TQ + woff, r32);
        #pragma unroll
        for (int j = 0; j < 32; j++) r32[j] = f2tf(qp[32+j]);
        STTM_X32(tb + TQ + 32 + woff, r32);
        uint32_t r8[8];
        #pragma unroll
        for (int j = 0; j < 8; j++) r8[j] = f2tf(qp[64+j]);
        STTM_X8(tb + TQ + 64 + woff, r8);
        TC_WAIT_ST();
        TC_FENCE_B();
    }
    __syncthreads();

    uint64_t kdesc[2] = { mkdesc(kbuf[0]), mkdesc(kbuf[1]) };
    uint64_t vdesc[2] = { mkdesc(kbuf[0] + KBYTES), mkdesc(kbuf[1] + KBYTES) };
    int ktn = (qt >= 8) ? 17 : (2*qt + 2);
    int phF[2] = {0,0}, ph1 = 0, ph2 = 0;

    for (int t = 0; t < ktn; t++) {
        int bsel = t & 1;
        if (t > 0) { MB_WAIT(mb2, ph2); ph2 ^= 1; }   // MMA2(t-1) done: TSP + old buf free

        if (tid == 0 && t+1 < ktn) {
            int nb = (t+1) & 1;
            MB_EXPECT_TX(mbF[nb], TILE_BYTES);
            bulk_g2s(kbuf[nb],          ktiles + (size_t)(t+1)*KWORDS, KBYTES, mbF[nb]);
            bulk_g2s(kbuf[nb] + KBYTES, vtiles + (size_t)(t+1)*VWORDS, TILE_BYTES - KBYTES, mbF[nb]);
        }

        MB_WAIT(mbF[bsel], phF[bsel]); phF[bsel] ^= 1;

        if (wid == 4) {
            TC_FENCE_A();
            if (elect1()) {
                #pragma unroll
                for (int s8 = 0; s8 < 9; s8++) {
                    uint64_t bd = kdesc[bsel] + (uint64_t)((s8>>2)*512 + (s8&3)*2);
                    mma_tf32_ts(tb + TSP, tb + TQ + s8*8, bd, IDESC_QK, s8 > 0);
                }
                TC_COMMIT(mb1);
            }
        }
        MB_WAIT(mb1, ph1); ph1 ^= 1;

        if (tid < 128) {
            TC_FENCE_A();
            uint32_t woff = (uint32_t)(tid >> 5) << 21;
            uint32_t sA[32], sB[32];
            LDTM_X32(sA, tb + TSP);
            LDTM_X32(sB, tb + TSP + 32);
            TC_WAIT_LD();
            int k0 = t*64;
            float lsum = 0.f;
            #pragma unroll
            for (int j = 0; j < 32; j++) {
                float sc = __uint_as_float(sA[j]);
                float p  = (k0 + j <= qeff) ? ex2f_(fmaf(sc, L2E, -1.5f*L2E)) : 0.f;
                sA[j] = f2tf(p);
                lsum += __uint_as_float(sA[j]);
            }
            #pragma unroll
            for (int j = 0; j < 32; j++) {
                float sc = __uint_as_float(sB[j]);
                float p  = (k0 + 32 + j <= qeff) ? ex2f_(fmaf(sc, L2E, -1.5f*L2E)) : 0.f;
                sB[j] = f2tf(p);
                lsum += __uint_as_float(sB[j]);
            }
            sum += lsum;
            STTM_X32(tb + TSP + woff, sA);
            STTM_X32(tb + TSP + 32 + woff, sB);
            TC_WAIT_ST();
            TC_FENCE_B();
        }
        __syncthreads();

        if (wid == 4) {
            TC_FENCE_A();
            if (elect1()) {
                #pragma unroll
                for (int s8 = 0; s8 < 8; s8++) {
                    uint64_t bd = vdesc[bsel] + (uint64_t)((s8>>2)*576 + (s8&3)*2);
                    mma_tf32_ts(tb + TO, tb + TSP + s8*8, bd, IDESC_PV, (t > 0) || (s8 > 0));
                }
                TC_COMMIT(mb2);
            }
        }
    }
    MB_WAIT(mb2, ph2); ph2 ^= 1;

    // ---- output: (O + selfp*V[q]) / sum, staged for coalesced writes ----
    uint32_t o1[32], o2[32], o3[8];
    if (tid < 128) {
        TC_FENCE_A();
        LDTM_X32(o1, tb + TO);
        LDTM_X32(o2, tb + TO + 32);
        LDTM_X8 (o3, tb + TO + 64);
        TC_WAIT_LD();
    }
    __syncthreads();   // loop buffers no longer read -> reuse as stages

    {   // stage raw V rows of this q-tile (coalesced)
        const float* vb = v + ((size_t)bh*S_ + q0)*D_;
        for (int i = tid; i < 128*D_; i += 256) {
            int r = i / D_, d = i - r*D_;
            stage1[r*77 + d] = vb[i];
        }
    }
    __syncthreads();

    if (tid < 128) {
        float* op = stage0 + tid*77;
        if (q < 576 || sum == 0.f) {
            #pragma unroll
            for (int d = 0; d < D_; d++) op[d] = 0.f;
        } else {
            float inv = 1.f / sum;
            const float* vp = stage1 + tid*77;
            #pragma unroll
            for (int d = 0; d < 32; d++) op[d]    = (__uint_as_float(o1[d]) + selfp*vp[d])    * inv;
            #pragma unroll
            for (int d = 0; d < 32; d++) op[32+d] = (__uint_as_float(o2[d]) + selfp*vp[32+d]) * inv;
            #pragma unroll
            for (int d = 0; d < 8; d++)  op[64+d] = (__uint_as_float(o3[d]) + selfp*vp[64+d]) * inv;
        }
    }
    __syncthreads();

    for (int i = tid; i < 128*D_; i += 256) {
        int r = i / D_, d = i - r*D_;
        obase[q0*D_ + i] = stage0[r*77 + d];
    }

    __syncthreads();
    if (wid == 4) {
        TC_RELINQ();
        TC_DEALLOC(tb, 256);
    }
#endif
}

extern "C" void kernel_launch(void* const* d_in, const int* in_sizes, int n_in,
                              void* d_out, int out_size)
{
    const float* q        = (const float*)d_in[0];
    const float* k        = (const float*)d_in[1];
    const float* v        = (const float*)d_in[2];
    const float* pos      = (const float*)d_in[3];
    const float* pos_orig = (const float*)d_in[4];
    const float* tim      = (const float*)d_in[5];
    const float* freqs    = (const float*)d_in[6];
    const float* t_freqs  = (const float*)d_in[7];
    const float* scale    = (const float*)d_in[8];
    float* out = (float*)d_out;

    const int smem_bytes = 2*TILE_BYTES + 1024;   // 87040
    cudaFuncSetAttribute(attn_tc, cudaFuncAttributeMaxDynamicSharedMemorySize, smem_bytes);

    prep_kernel<<<(BHS_*32)/256, 256>>>(q, k, pos, pos_orig, tim, freqs, t_freqs, scale);
    vprep_kernel<<<dim3(32, 32), 256>>>(v);

    dim3 grid(S_/128, B_*H_);
    attn_tc<<<grid, 256, smem_bytes>>>(v, out);
}